// round 7
// baseline (speedup 1.0000x reference)
#include <cuda_runtime.h>
#include <math.h>

#define NPTS 1024
#define TPB  256
#define PPT  4
#define BPC  4            // batches per CTA
#define MAXB 8192

__device__ float g_partial[MAXB];
__device__ unsigned g_count = 0;

__device__ __forceinline__ float warp_sum(float v) {
#pragma unroll
    for (int o = 16; o; o >>= 1) v += __shfl_xor_sync(0xffffffffu, v, o);
    return v;
}

// Value-parallel reduction of 16 per-lane accumulators across a warp using
// only 16 shuffles. On return, lane (2*v) holds total of value v.
__device__ __forceinline__ float multi_reduce16(const float acc[16], int lane) {
    float rA[8];
#pragma unroll
    for (int k = 0; k < 8; k++) {
        bool lo = (lane & 16) == 0;
        float keep = lo ? acc[k] : acc[k + 8];
        float send = lo ? acc[k + 8] : acc[k];
        rA[k] = keep + __shfl_xor_sync(0xffffffffu, send, 16);
    }
    float rB[4];
#pragma unroll
    for (int k = 0; k < 4; k++) {
        bool lo = (lane & 8) == 0;
        float keep = lo ? rA[k] : rA[k + 4];
        float send = lo ? rA[k + 4] : rA[k];
        rB[k] = keep + __shfl_xor_sync(0xffffffffu, send, 8);
    }
    float rC[2];
#pragma unroll
    for (int k = 0; k < 2; k++) {
        bool lo = (lane & 4) == 0;
        float keep = lo ? rB[k] : rB[k + 2];
        float send = lo ? rB[k + 2] : rB[k];
        rC[k] = keep + __shfl_xor_sync(0xffffffffu, send, 4);
    }
    float rD;
    {
        bool lo = (lane & 2) == 0;
        float keep = lo ? rC[0] : rC[1];
        float send = lo ? rC[1] : rC[0];
        rD = keep + __shfl_xor_sync(0xffffffffu, send, 2);
    }
    return rD + __shfl_xor_sync(0xffffffffu, rD, 1);
}

__device__ __forceinline__ void eigvec3(const float B[3][3], float lam, float v[3]) {
    float r0x = B[0][0] - lam, r0y = B[0][1],        r0z = B[0][2];
    float r1x = B[0][1],        r1y = B[1][1] - lam, r1z = B[1][2];
    float r2x = B[0][2],        r2y = B[1][2],        r2z = B[2][2] - lam;

    float c0x = r0y * r1z - r0z * r1y, c0y = r0z * r1x - r0x * r1z, c0z = r0x * r1y - r0y * r1x;
    float c1x = r0y * r2z - r0z * r2y, c1y = r0z * r2x - r0x * r2z, c1z = r0x * r2y - r0y * r2x;
    float c2x = r1y * r2z - r1z * r2y, c2y = r1z * r2x - r1x * r2z, c2z = r1x * r2y - r1y * r2x;

    float n0 = c0x * c0x + c0y * c0y + c0z * c0z;
    float n1 = c1x * c1x + c1y * c1y + c1z * c1z;
    float n2 = c2x * c2x + c2y * c2y + c2z * c2z;

    float bx = c0x, by = c0y, bz = c0z, bn = n0;
    if (n1 > bn) { bx = c1x; by = c1y; bz = c1z; bn = n1; }
    if (n2 > bn) { bx = c2x; by = c2y; bz = c2z; bn = n2; }
    float inv = rsqrtf(fmaxf(bn, 1e-30f));
    v[0] = bx * inv; v[1] = by * inv; v[2] = bz * inv;
}

// Closed-form Kabsch from the 15 raw sums; writes R (row-major) + mu_p + mu_q.
__device__ __forceinline__ void kabsch_solve(const float tot[15], float* sRm) {
    const float inv_n = 1.0f / (float)NPTS;
    float mup[3] = {tot[0] * inv_n, tot[1] * inv_n, tot[2] * inv_n};
    float muq[3] = {tot[3] * inv_n, tot[4] * inv_n, tot[5] * inv_n};

    float M[3][3];
#pragma unroll
    for (int i = 0; i < 3; i++)
#pragma unroll
        for (int j = 0; j < 3; j++)
            M[i][j] = tot[6 + 3 * i + j] - (float)NPTS * muq[i] * mup[j];

    float sc = 1e-30f;
#pragma unroll
    for (int i = 0; i < 3; i++)
#pragma unroll
        for (int j = 0; j < 3; j++) sc = fmaxf(sc, fabsf(M[i][j]));
    float invsc = __fdividef(1.0f, sc);
    float a[3][3];
#pragma unroll
    for (int i = 0; i < 3; i++)
#pragma unroll
        for (int j = 0; j < 3; j++) a[i][j] = M[i][j] * invsc;

    float B[3][3];
#pragma unroll
    for (int i = 0; i < 3; i++)
#pragma unroll
        for (int j = i; j < 3; j++) {
            float s = 0.f;
#pragma unroll
            for (int k = 0; k < 3; k++) s += a[k][i] * a[k][j];
            B[i][j] = s; B[j][i] = s;
        }

    float qm = (B[0][0] + B[1][1] + B[2][2]) * (1.0f / 3.0f);
    float b00 = B[0][0] - qm, b11 = B[1][1] - qm, b22 = B[2][2] - qm;
    float p1 = B[0][1] * B[0][1] + B[0][2] * B[0][2] + B[1][2] * B[1][2];
    float p2 = b00 * b00 + b11 * b11 + b22 * b22 + 2.0f * p1;
    float pp = sqrtf(p2 * (1.0f / 6.0f) + 1e-30f);
    float invp = __fdividef(1.0f, pp);
    float c00 = b00 * invp, c11 = b11 * invp, c22 = b22 * invp;
    float c01 = B[0][1] * invp, c02 = B[0][2] * invp, c12 = B[1][2] * invp;
    float detC = c00 * (c11 * c22 - c12 * c12)
               - c01 * (c01 * c22 - c12 * c02)
               + c02 * (c01 * c12 - c11 * c02);
    float r = fminf(fmaxf(0.5f * detC, -1.0f), 1.0f);
    float phi = acosf(r) * (1.0f / 3.0f);
    float lam0 = qm + 2.0f * pp * cosf(phi);
    float lam2 = qm + 2.0f * pp * cosf(phi + 2.0943951024f);
    float lam1 = 3.0f * qm - lam0 - lam2;

    float v0[3], v2[3], v1[3];
    eigvec3(B, lam0, v0);
    eigvec3(B, lam2, v2);
    v1[0] = v2[1] * v0[2] - v2[2] * v0[1];
    v1[1] = v2[2] * v0[0] - v2[0] * v0[2];
    v1[2] = v2[0] * v0[1] - v2[1] * v0[0];
    float n1 = v1[0] * v1[0] + v1[1] * v1[1] + v1[2] * v1[2];
    float in1 = rsqrtf(fmaxf(n1, 1e-30f));
    v1[0] *= in1; v1[1] *= in1; v1[2] *= in1;

    float det = a[0][0] * (a[1][1] * a[2][2] - a[1][2] * a[2][1]) -
                a[0][1] * (a[1][0] * a[2][2] - a[1][2] * a[2][0]) +
                a[0][2] * (a[1][0] * a[2][1] - a[1][1] * a[2][0]);
    float dsgn = (det >= 0.f) ? 1.f : -1.f;

    float cv0 = rsqrtf(fmaxf(lam0, 1e-20f));
    float cv1 = rsqrtf(fmaxf(lam1, 1e-20f));
    float cv2 = dsgn * rsqrtf(fmaxf(lam2, 1e-20f));

    float G[3][3];
#pragma unroll
    for (int i = 0; i < 3; i++)
#pragma unroll
        for (int j = 0; j < 3; j++)
            G[i][j] = cv0 * v0[i] * v0[j] + cv1 * v1[i] * v1[j] + cv2 * v2[i] * v2[j];
#pragma unroll
    for (int i = 0; i < 3; i++)
#pragma unroll
        for (int j = 0; j < 3; j++) {
            float s = 0.f;
#pragma unroll
            for (int k = 0; k < 3; k++) s += a[i][k] * G[k][j];
            sRm[3 * i + j] = s;
        }
    sRm[9]  = mup[0]; sRm[10] = mup[1]; sRm[11] = mup[2];
    sRm[12] = muq[0]; sRm[13] = muq[1]; sRm[14] = muq[2];
}

__global__ __launch_bounds__(TPB, 4) void tm_kernel(const float* __restrict__ pred,
                                                    const float* __restrict__ act,
                                                    float d0sq,
                                                    float* __restrict__ out,
                                                    float scale) {
    __shared__ float red[BPC][8][16];
    __shared__ float sRm[BPC][16];
    __shared__ float red2[8];
    __shared__ int s_last;

    const int tid = threadIdx.x;
    const int wid = tid >> 5;
    const int lane = tid & 31;
    const int bb = blockIdx.x * BPC;

    // ---- Phase 1: four batches streamed back-to-back (DRAM stays busy) ----
#pragma unroll
    for (int j = 0; j < BPC; j++) {
        const float4* p4 = (const float4*)(pred + (size_t)(bb + j) * 3 * NPTS);
        const float4* q4 = (const float4*)(act + (size_t)(bb + j) * 3 * NPTS);
        float4 pa = p4[3 * tid + 0], pb = p4[3 * tid + 1], pc = p4[3 * tid + 2];
        float4 qa = q4[3 * tid + 0], qb = q4[3 * tid + 1], qc = q4[3 * tid + 2];
        float px[PPT] = {pa.x, pa.w, pb.z, pc.y};
        float py[PPT] = {pa.y, pb.x, pb.w, pc.z};
        float pz[PPT] = {pa.z, pb.y, pc.x, pc.w};
        float qx[PPT] = {qa.x, qa.w, qb.z, qc.y};
        float qy[PPT] = {qa.y, qb.x, qb.w, qc.z};
        float qz[PPT] = {qa.z, qb.y, qc.x, qc.w};

        float acc[16];
#pragma unroll
        for (int v = 0; v < 16; v++) acc[v] = 0.f;
#pragma unroll
        for (int k = 0; k < PPT; k++) {
            acc[0] += px[k]; acc[1] += py[k]; acc[2] += pz[k];
            acc[3] += qx[k]; acc[4] += qy[k]; acc[5] += qz[k];
            acc[6] += qx[k] * px[k]; acc[7] += qx[k] * py[k]; acc[8] += qx[k] * pz[k];
            acc[9] += qy[k] * px[k]; acc[10] += qy[k] * py[k]; acc[11] += qy[k] * pz[k];
            acc[12] += qz[k] * px[k]; acc[13] += qz[k] * py[k]; acc[14] += qz[k] * pz[k];
        }
        float tsum = multi_reduce16(acc, lane);
        int v = lane >> 1;
        if ((lane & 1) == 0 && v < 15) red[j][wid][v] = tsum;
    }
    __syncthreads();

    // ---- Warps 0..3: totals + solve for batch `wid` (4 solves in parallel) ----
    if (wid < BPC) {
        float t = 0.f;
        if (lane < 15) {
#pragma unroll
            for (int w = 0; w < TPB / 32; w++) t += red[wid][w][lane];
        }
        float tot[15];
#pragma unroll
        for (int v = 0; v < 15; v++) tot[v] = __shfl_sync(0xffffffffu, t, v);
        if (lane == 0) kabsch_solve(tot, &sRm[wid][0]);
    }
    __syncthreads();

    // ---- Phase 2: four batches reloaded from L2, fsums folded together ----
    const float EPS = 1e-8f;
    float fsum = 0.f;
#pragma unroll
    for (int j = 0; j < BPC; j++) {
        const float4* p4 = (const float4*)(pred + (size_t)(bb + j) * 3 * NPTS);
        const float4* q4 = (const float4*)(act + (size_t)(bb + j) * 3 * NPTS);
        const float R00 = sRm[j][0], R01 = sRm[j][1], R02 = sRm[j][2];
        const float R10 = sRm[j][3], R11 = sRm[j][4], R12 = sRm[j][5];
        const float R20 = sRm[j][6], R21 = sRm[j][7], R22 = sRm[j][8];
        const float mup0 = sRm[j][9],  mup1 = sRm[j][10], mup2 = sRm[j][11];
        const float muq0 = sRm[j][12], muq1 = sRm[j][13], muq2 = sRm[j][14];

        float4 ra = __ldcg(&p4[3 * tid + 0]);
        float4 rb = __ldcg(&p4[3 * tid + 1]);
        float4 rc = __ldcg(&p4[3 * tid + 2]);
        float4 sa = __ldcg(&q4[3 * tid + 0]);
        float4 sb = __ldcg(&q4[3 * tid + 1]);
        float4 scq = __ldcg(&q4[3 * tid + 2]);
        float ppx[PPT] = {ra.x, ra.w, rb.z, rc.y};
        float ppy[PPT] = {ra.y, rb.x, rb.w, rc.z};
        float ppz[PPT] = {ra.z, rb.y, rc.x, rc.w};
        float qqx[PPT] = {sa.x, sa.w, sb.z, scq.y};
        float qqy[PPT] = {sa.y, sb.x, sb.w, scq.z};
        float qqz[PPT] = {sa.z, sb.y, scq.x, scq.w};

#pragma unroll
        for (int k = 0; k < PPT; k++) {
            float cx = qqx[k] - muq0;
            float cy = qqy[k] - muq1;
            float cz = qqz[k] - muq2;
            float ax = cx * R00 + cy * R10 + cz * R20;
            float ay = cx * R01 + cy * R11 + cz * R21;
            float az = cx * R02 + cy * R12 + cz * R22;
            float dx = (ppx[k] - mup0) - ax + EPS;
            float dy = (ppy[k] - mup1) - ay + EPS;
            float dz = (ppz[k] - mup2) - az + EPS;
            float d2 = dx * dx + dy * dy + dz * dz;
            fsum += __fdividef(d0sq, d0sq + d2);
        }
    }
    fsum = warp_sum(fsum);
    if (lane == 0) red2[wid] = fsum;
    __syncthreads();

    // ---- Per-CTA partial + fused deterministic final reduction ----
    if (tid == 0) {
        float t = 0.f;
#pragma unroll
        for (int w = 0; w < TPB / 32; w++) t += red2[w];
        g_partial[blockIdx.x] = t;
        __threadfence();
        unsigned r = atomicAdd(&g_count, 1u);
        s_last = (r == gridDim.x - 1) ? 1 : 0;
    }
    __syncthreads();

    if (s_last) {
        const int nb = gridDim.x;
        float v = 0.f;
        for (int i = tid; i < nb; i += TPB) v += __ldcg(&g_partial[i]);
        v = warp_sum(v);
        if (lane == 0) red2[wid] = v;
        __syncthreads();
        if (tid == 0) {
            float t = 0.f;
#pragma unroll
            for (int w = 0; w < TPB / 32; w++) t += red2[w];
            out[0] = -t * scale;
            g_count = 0;  // reset for replay determinism
        }
    }
}

extern "C" void kernel_launch(void* const* d_in, const int* in_sizes, int n_in,
                              void* d_out, int out_size) {
    const float* pred = (const float*)d_in[0];
    const float* act = (const float*)d_in[1];
    float* out = (float*)d_out;

    int b = in_sizes[0] / (3 * NPTS);
    if (b > MAXB) b = MAXB;
    int nblk = b / BPC;   // b = 2048 -> 512 CTAs

    double d0 = 1.24 * cbrt((double)NPTS - 15.0) - 1.8;
    float d0sq = (float)(d0 * d0);
    float scale = 1.0f / ((float)b * (float)NPTS);

    tm_kernel<<<nblk, TPB>>>(pred, act, d0sq, out, scale);
}

// round 8
// speedup vs baseline: 1.6824x; 1.6824x over previous
#include <cuda_runtime.h>
#include <math.h>

#define NPTS 1024
#define TPB  128
#define WPB  (TPB / 32)    // warps (= batches) per CTA
#define CHK  8             // chunks per thread (8 * 4 points = 32 points)
#define MAXB 8192

__device__ float g_partial[MAXB];
__device__ unsigned g_count = 0;

__device__ __forceinline__ float warp_sum(float v) {
#pragma unroll
    for (int o = 16; o; o >>= 1) v += __shfl_xor_sync(0xffffffffu, v, o);
    return v;
}

// Value-parallel reduction of 16 per-lane accumulators across a warp using
// only 16 shuffles. On return, lane (2*v) holds total of value v.
__device__ __forceinline__ float multi_reduce16(const float acc[16], int lane) {
    float rA[8];
#pragma unroll
    for (int k = 0; k < 8; k++) {
        bool lo = (lane & 16) == 0;
        float keep = lo ? acc[k] : acc[k + 8];
        float send = lo ? acc[k + 8] : acc[k];
        rA[k] = keep + __shfl_xor_sync(0xffffffffu, send, 16);
    }
    float rB[4];
#pragma unroll
    for (int k = 0; k < 4; k++) {
        bool lo = (lane & 8) == 0;
        float keep = lo ? rA[k] : rA[k + 4];
        float send = lo ? rA[k + 4] : rA[k];
        rB[k] = keep + __shfl_xor_sync(0xffffffffu, send, 8);
    }
    float rC[2];
#pragma unroll
    for (int k = 0; k < 2; k++) {
        bool lo = (lane & 4) == 0;
        float keep = lo ? rB[k] : rB[k + 2];
        float send = lo ? rB[k + 2] : rB[k];
        rC[k] = keep + __shfl_xor_sync(0xffffffffu, send, 4);
    }
    float rD;
    {
        bool lo = (lane & 2) == 0;
        float keep = lo ? rC[0] : rC[1];
        float send = lo ? rC[1] : rC[0];
        rD = keep + __shfl_xor_sync(0xffffffffu, send, 2);
    }
    return rD + __shfl_xor_sync(0xffffffffu, rD, 1);
}

__device__ __forceinline__ void eigvec3(const float B[3][3], float lam, float v[3]) {
    float r0x = B[0][0] - lam, r0y = B[0][1],        r0z = B[0][2];
    float r1x = B[0][1],        r1y = B[1][1] - lam, r1z = B[1][2];
    float r2x = B[0][2],        r2y = B[1][2],        r2z = B[2][2] - lam;

    float c0x = r0y * r1z - r0z * r1y, c0y = r0z * r1x - r0x * r1z, c0z = r0x * r1y - r0y * r1x;
    float c1x = r0y * r2z - r0z * r2y, c1y = r0z * r2x - r0x * r2z, c1z = r0x * r2y - r0y * r2x;
    float c2x = r1y * r2z - r1z * r2y, c2y = r1z * r2x - r1x * r2z, c2z = r1x * r2y - r1y * r2x;

    float n0 = c0x * c0x + c0y * c0y + c0z * c0z;
    float n1 = c1x * c1x + c1y * c1y + c1z * c1z;
    float n2 = c2x * c2x + c2y * c2y + c2z * c2z;

    float bx = c0x, by = c0y, bz = c0z, bn = n0;
    if (n1 > bn) { bx = c1x; by = c1y; bz = c1z; bn = n1; }
    if (n2 > bn) { bx = c2x; by = c2y; bz = c2z; bn = n2; }
    float inv = rsqrtf(fmaxf(bn, 1e-30f));
    v[0] = bx * inv; v[1] = by * inv; v[2] = bz * inv;
}

// Closed-form Kabsch from 15 raw sums -> R (row-major) + mu_p + mu_q.
// Executed redundantly by all 32 lanes (pure SIMD, no divergence).
__device__ __forceinline__ void kabsch_solve(const float tot[15], float sRm[15]) {
    const float inv_n = 1.0f / (float)NPTS;
    float mup[3] = {tot[0] * inv_n, tot[1] * inv_n, tot[2] * inv_n};
    float muq[3] = {tot[3] * inv_n, tot[4] * inv_n, tot[5] * inv_n};

    float M[3][3];
#pragma unroll
    for (int i = 0; i < 3; i++)
#pragma unroll
        for (int j = 0; j < 3; j++)
            M[i][j] = tot[6 + 3 * i + j] - (float)NPTS * muq[i] * mup[j];

    float sc = 1e-30f;
#pragma unroll
    for (int i = 0; i < 3; i++)
#pragma unroll
        for (int j = 0; j < 3; j++) sc = fmaxf(sc, fabsf(M[i][j]));
    float invsc = __fdividef(1.0f, sc);
    float a[3][3];
#pragma unroll
    for (int i = 0; i < 3; i++)
#pragma unroll
        for (int j = 0; j < 3; j++) a[i][j] = M[i][j] * invsc;

    float B[3][3];
#pragma unroll
    for (int i = 0; i < 3; i++)
#pragma unroll
        for (int j = i; j < 3; j++) {
            float s = 0.f;
#pragma unroll
            for (int k = 0; k < 3; k++) s += a[k][i] * a[k][j];
            B[i][j] = s; B[j][i] = s;
        }

    float qm = (B[0][0] + B[1][1] + B[2][2]) * (1.0f / 3.0f);
    float b00 = B[0][0] - qm, b11 = B[1][1] - qm, b22 = B[2][2] - qm;
    float p1 = B[0][1] * B[0][1] + B[0][2] * B[0][2] + B[1][2] * B[1][2];
    float p2 = b00 * b00 + b11 * b11 + b22 * b22 + 2.0f * p1;
    float pp = sqrtf(p2 * (1.0f / 6.0f) + 1e-30f);
    float invp = __fdividef(1.0f, pp);
    float c00 = b00 * invp, c11 = b11 * invp, c22 = b22 * invp;
    float c01 = B[0][1] * invp, c02 = B[0][2] * invp, c12 = B[1][2] * invp;
    float detC = c00 * (c11 * c22 - c12 * c12)
               - c01 * (c01 * c22 - c12 * c02)
               + c02 * (c01 * c12 - c11 * c02);
    float r = fminf(fmaxf(0.5f * detC, -1.0f), 1.0f);
    float phi = acosf(r) * (1.0f / 3.0f);
    float lam0 = qm + 2.0f * pp * cosf(phi);
    float lam2 = qm + 2.0f * pp * cosf(phi + 2.0943951024f);
    float lam1 = 3.0f * qm - lam0 - lam2;

    float v0[3], v2[3], v1[3];
    eigvec3(B, lam0, v0);
    eigvec3(B, lam2, v2);
    v1[0] = v2[1] * v0[2] - v2[2] * v0[1];
    v1[1] = v2[2] * v0[0] - v2[0] * v0[2];
    v1[2] = v2[0] * v0[1] - v2[1] * v0[0];
    float n1 = v1[0] * v1[0] + v1[1] * v1[1] + v1[2] * v1[2];
    float in1 = rsqrtf(fmaxf(n1, 1e-30f));
    v1[0] *= in1; v1[1] *= in1; v1[2] *= in1;

    float det = a[0][0] * (a[1][1] * a[2][2] - a[1][2] * a[2][1]) -
                a[0][1] * (a[1][0] * a[2][2] - a[1][2] * a[2][0]) +
                a[0][2] * (a[1][0] * a[2][1] - a[1][1] * a[2][0]);
    float dsgn = (det >= 0.f) ? 1.f : -1.f;

    float cv0 = rsqrtf(fmaxf(lam0, 1e-20f));
    float cv1 = rsqrtf(fmaxf(lam1, 1e-20f));
    float cv2 = dsgn * rsqrtf(fmaxf(lam2, 1e-20f));

    float G[3][3];
#pragma unroll
    for (int i = 0; i < 3; i++)
#pragma unroll
        for (int j = 0; j < 3; j++)
            G[i][j] = cv0 * v0[i] * v0[j] + cv1 * v1[i] * v1[j] + cv2 * v2[i] * v2[j];
#pragma unroll
    for (int i = 0; i < 3; i++)
#pragma unroll
        for (int j = 0; j < 3; j++) {
            float s = 0.f;
#pragma unroll
            for (int k = 0; k < 3; k++) s += a[i][k] * G[k][j];
            sRm[3 * i + j] = s;
        }
    sRm[9]  = mup[0]; sRm[10] = mup[1]; sRm[11] = mup[2];
    sRm[12] = muq[0]; sRm[13] = muq[1]; sRm[14] = muq[2];
}

__global__ __launch_bounds__(TPB, 8) void tm_kernel(const float* __restrict__ pred,
                                                    const float* __restrict__ act,
                                                    float d0sq,
                                                    float* __restrict__ out,
                                                    float scale) {
    __shared__ float red2[WPB];
    __shared__ int s_last;

    const int tid = threadIdx.x;
    const int wid = tid >> 5;
    const int lane = tid & 31;
    const int batch = blockIdx.x * WPB + wid;

    const float4* p4 = (const float4*)(pred + (size_t)batch * 3 * NPTS);
    const float4* q4 = (const float4*)(act + (size_t)batch * 3 * NPTS);

    // ---- Phase 1: warp-private. 8 chunks x 4 points per thread. ----
    float acc[16];
#pragma unroll
    for (int v = 0; v < 16; v++) acc[v] = 0.f;
#pragma unroll
    for (int i = 0; i < CHK; i++) {
        int base = 96 * i + 3 * lane;
        float4 pa = p4[base + 0], pb = p4[base + 1], pc = p4[base + 2];
        float4 qa = q4[base + 0], qb = q4[base + 1], qc = q4[base + 2];
        float px[4] = {pa.x, pa.w, pb.z, pc.y};
        float py[4] = {pa.y, pb.x, pb.w, pc.z};
        float pz[4] = {pa.z, pb.y, pc.x, pc.w};
        float qx[4] = {qa.x, qa.w, qb.z, qc.y};
        float qy[4] = {qa.y, qb.x, qb.w, qc.z};
        float qz[4] = {qa.z, qb.y, qc.x, qc.w};
#pragma unroll
        for (int k = 0; k < 4; k++) {
            acc[0] += px[k]; acc[1] += py[k]; acc[2] += pz[k];
            acc[3] += qx[k]; acc[4] += qy[k]; acc[5] += qz[k];
            acc[6] += qx[k] * px[k]; acc[7] += qx[k] * py[k]; acc[8] += qx[k] * pz[k];
            acc[9] += qy[k] * px[k]; acc[10] += qy[k] * py[k]; acc[11] += qy[k] * pz[k];
            acc[12] += qz[k] * px[k]; acc[13] += qz[k] * py[k]; acc[14] += qz[k] * pz[k];
        }
    }

    // ---- Warp reduction (16 shfl) + broadcast totals to all lanes ----
    float tsum = multi_reduce16(acc, lane);
    float tot[15];
#pragma unroll
    for (int v = 0; v < 15; v++) tot[v] = __shfl_sync(0xffffffffu, tsum, 2 * v);

    // ---- All lanes solve redundantly (SIMD, no barrier, no broadcast) ----
    float sRm[15];
    kabsch_solve(tot, sRm);
    const float R00 = sRm[0], R01 = sRm[1], R02 = sRm[2];
    const float R10 = sRm[3], R11 = sRm[4], R12 = sRm[5];
    const float R20 = sRm[6], R21 = sRm[7], R22 = sRm[8];
    const float mup0 = sRm[9],  mup1 = sRm[10], mup2 = sRm[11];
    const float muq0 = sRm[12], muq1 = sRm[13], muq2 = sRm[14];
    const float EPS = 1e-8f;

    // ---- Phase 2: reload own chunks from L2, fold TM sum ----
    float fsum = 0.f;
#pragma unroll
    for (int i = 0; i < CHK; i++) {
        int base = 96 * i + 3 * lane;
        float4 ra = __ldcg(&p4[base + 0]);
        float4 rb = __ldcg(&p4[base + 1]);
        float4 rc = __ldcg(&p4[base + 2]);
        float4 sa = __ldcg(&q4[base + 0]);
        float4 sb = __ldcg(&q4[base + 1]);
        float4 scq = __ldcg(&q4[base + 2]);
        float ppx[4] = {ra.x, ra.w, rb.z, rc.y};
        float ppy[4] = {ra.y, rb.x, rb.w, rc.z};
        float ppz[4] = {ra.z, rb.y, rc.x, rc.w};
        float qqx[4] = {sa.x, sa.w, sb.z, scq.y};
        float qqy[4] = {sa.y, sb.x, sb.w, scq.z};
        float qqz[4] = {sa.z, sb.y, scq.x, scq.w};
#pragma unroll
        for (int k = 0; k < 4; k++) {
            float cx = qqx[k] - muq0;
            float cy = qqy[k] - muq1;
            float cz = qqz[k] - muq2;
            float ax = cx * R00 + cy * R10 + cz * R20;
            float ay = cx * R01 + cy * R11 + cz * R21;
            float az = cx * R02 + cy * R12 + cz * R22;
            float dx = (ppx[k] - mup0) - ax + EPS;
            float dy = (ppy[k] - mup1) - ay + EPS;
            float dz = (ppz[k] - mup2) - az + EPS;
            float d2 = dx * dx + dy * dy + dz * dz;
            fsum += __fdividef(d0sq, d0sq + d2);
        }
    }
    fsum = warp_sum(fsum);
    if (lane == 0) g_partial[batch] = fsum;

    // ---- Fused deterministic final reduction (last CTA) ----
    __syncthreads();
    if (tid == 0) {
        __threadfence();
        unsigned r = atomicAdd(&g_count, 1u);
        s_last = (r == gridDim.x - 1) ? 1 : 0;
    }
    __syncthreads();

    if (s_last) {
        const int nb = gridDim.x * WPB;
        float v = 0.f;
        for (int i = tid; i < nb; i += TPB) v += __ldcg(&g_partial[i]);
        v = warp_sum(v);
        if (lane == 0) red2[wid] = v;
        __syncthreads();
        if (tid == 0) {
            float t = 0.f;
#pragma unroll
            for (int w = 0; w < WPB; w++) t += red2[w];
            out[0] = -t * scale;
            g_count = 0;  // reset for replay determinism
        }
    }
}

extern "C" void kernel_launch(void* const* d_in, const int* in_sizes, int n_in,
                              void* d_out, int out_size) {
    const float* pred = (const float*)d_in[0];
    const float* act = (const float*)d_in[1];
    float* out = (float*)d_out;

    int b = in_sizes[0] / (3 * NPTS);
    if (b > MAXB) b = MAXB;
    int nblk = b / WPB;   // b = 2048 -> 512 CTAs of 128 threads

    double d0 = 1.24 * cbrt((double)NPTS - 15.0) - 1.8;
    float d0sq = (float)(d0 * d0);
    float scale = 1.0f / ((float)b * (float)NPTS);

    tm_kernel<<<nblk, TPB>>>(pred, act, d0sq, out, scale);
}